// round 15
// baseline (speedup 1.0000x reference)
#include <cuda_runtime.h>
#include <cuda_fp16.h>
#include <math.h>
#include <stdint.h>

#define B_ 2
#define L_ 2048
#define D_ 1024
#define H_ 16
#define DH_ 64
#define FF_ 4096
#define EPS_ 1e-5f
#define D3_ 3072
#define LOG2E 1.4426950408889634f

// ---------------- scratch (device globals) ----------------
__device__ __half g_h[B_ * L_ * D_];
__device__ __half g_qkv[B_ * L_ * D3_];
__device__ __half g_ao[B_ * L_ * D_];
__device__ float  g_x2[B_ * L_ * D_];
__device__ __half g_ff[B_ * L_ * FF_];
__device__ __half g_wqkv[D_ * D3_];    // [1024][3072] N-major
__device__ __half g_woh[D_ * D_];
__device__ __half g_w1h[D_ * FF_];
__device__ __half g_w2h[FF_ * D_];

// ---------------- helpers ----------------
__device__ __forceinline__ uint32_t smem_u32(const void* p) {
    uint32_t a;
    asm("{ .reg .u64 t; cvta.to.shared.u64 t, %1; cvt.u32.u64 %0, t; }" : "=r"(a) : "l"(p));
    return a;
}
__device__ __forceinline__ void mma_f16(float* c, const uint32_t* a, uint32_t b0, uint32_t b1) {
    asm volatile(
        "mma.sync.aligned.m16n8k16.row.col.f32.f16.f16.f32 "
        "{%0,%1,%2,%3}, {%4,%5,%6,%7}, {%8,%9}, {%0,%1,%2,%3};"
        : "+f"(c[0]), "+f"(c[1]), "+f"(c[2]), "+f"(c[3])
        : "r"(a[0]), "r"(a[1]), "r"(a[2]), "r"(a[3]), "r"(b0), "r"(b1));
}
__device__ __forceinline__ void ldsm_x4(uint32_t* r, uint32_t addr) {
    asm volatile("ldmatrix.sync.aligned.m8n8.x4.shared.b16 {%0,%1,%2,%3}, [%4];"
        : "=r"(r[0]), "=r"(r[1]), "=r"(r[2]), "=r"(r[3]) : "r"(addr));
}
__device__ __forceinline__ void ldsm_x4_t(uint32_t* r, uint32_t addr) {
    asm volatile("ldmatrix.sync.aligned.m8n8.x4.trans.shared.b16 {%0,%1,%2,%3}, [%4];"
        : "=r"(r[0]), "=r"(r[1]), "=r"(r[2]), "=r"(r[3]) : "r"(addr));
}
__device__ __forceinline__ float ex2(float x) {
    float r;
    asm("ex2.approx.f32 %0, %1;" : "=f"(r) : "f"(x));
    return r;
}

#define CP_ASYNC16(dst, src) \
    asm volatile("cp.async.cg.shared.global [%0], [%1], 16;" :: "r"(dst), "l"(src))
#define CP_COMMIT() asm volatile("cp.async.commit_group;" ::: "memory")
#define CP_WAIT(n)  asm volatile("cp.async.wait_group %0;" :: "n"(n) : "memory")

// ---------------- fused prep: LN1(+pos) AND weight convert in one launch ----------------
__global__ void prep_kernel(const float* __restrict__ x,
                            const float* __restrict__ gamma,
                            const float* __restrict__ beta,
                            const float* __restrict__ pos,
                            __half* __restrict__ out,
                            const float* __restrict__ Wq, const float* __restrict__ Wk,
                            const float* __restrict__ Wv, const float* __restrict__ Wo,
                            const float* __restrict__ W1, const float* __restrict__ W2,
                            __half* __restrict__ wqkv, __half* __restrict__ woh,
                            __half* __restrict__ w1h, __half* __restrict__ w2h) {
    int t = threadIdx.x;
    if (blockIdx.x < (unsigned)(B_ * L_)) {
        int row = blockIdx.x;
        int l = row & (L_ - 1);
        const float* xr = x + (size_t)row * D_;
        float4 v = *(const float4*)(xr + t * 4);

        float s = v.x + v.y + v.z + v.w;
        float sq = v.x * v.x + v.y * v.y + v.z * v.z + v.w * v.w;
        #pragma unroll
        for (int o = 16; o > 0; o >>= 1) {
            s  += __shfl_down_sync(0xffffffffu, s,  o);
            sq += __shfl_down_sync(0xffffffffu, sq, o);
        }
        __shared__ float ss[8], sqs[8], stats[2];
        int wid = t >> 5, lane = t & 31;
        if (lane == 0) { ss[wid] = s; sqs[wid] = sq; }
        __syncthreads();
        if (t == 0) {
            float S = 0.f, SQ = 0.f;
            #pragma unroll
            for (int i = 0; i < 8; i++) { S += ss[i]; SQ += sqs[i]; }
            float mu = S / (float)D_;
            float var = SQ / (float)D_ - mu * mu;
            stats[0] = mu;
            stats[1] = rsqrtf(var + EPS_);
        }
        __syncthreads();
        float mu = stats[0], rs = stats[1];

        float4 g4 = *(const float4*)(gamma + t * 4);
        float4 b4 = *(const float4*)(beta + t * 4);
        float4 r;
        r.x = (v.x - mu) * rs * g4.x + b4.x;
        r.y = (v.y - mu) * rs * g4.y + b4.y;
        r.z = (v.z - mu) * rs * g4.z + b4.z;
        r.w = (v.w - mu) * rs * g4.w + b4.w;
        float4 p4 = *(const float4*)(pos + (size_t)l * D_ + t * 4);
        r.x += p4.x; r.y += p4.y; r.z += p4.z; r.w += p4.w;
        __half2 h0 = __floats2half2_rn(r.x, r.y);
        __half2 h1 = __floats2half2_rn(r.z, r.w);
        *(uint2*)(out + (size_t)row * D_ + t * 4) = make_uint2(*(uint32_t*)&h0, *(uint32_t*)&h1);
    } else {
        const int M1 = 1 << 20;
        size_t i = ((size_t)(blockIdx.x - B_ * L_) * 256 + t) * 4;
        const float* src;
        __half* dst;
        size_t soff, doff;
        if (i < (size_t)3 * M1) {
            int which = (int)(i >> 20);
            size_t li = i & (M1 - 1);
            int k = (int)(li >> 10), n = (int)(li & 1023);
            src = (which == 0) ? Wq : (which == 1) ? Wk : Wv;
            soff = li;
            dst = wqkv;
            doff = (size_t)k * D3_ + which * 1024 + n;
        } else if (i < (size_t)4 * M1) {
            src = Wo; soff = i - 3 * M1; dst = woh; doff = soff;
        } else if (i < (size_t)8 * M1) {
            src = W1; soff = i - 4 * M1; dst = w1h; doff = soff;
        } else {
            src = W2; soff = i - (size_t)8 * M1; dst = w2h; doff = soff;
        }
        float4 v = *(const float4*)(src + soff);
        __half2 h0 = __floats2half2_rn(v.x, v.y);
        __half2 h1 = __floats2half2_rn(v.z, v.w);
        *(uint2*)(dst + doff) = make_uint2(*(uint32_t*)&h0, *(uint32_t*)&h1);
    }
}

// ---------------- LayerNorm (standalone, for LN2), output fp16 ----------------
__global__ void ln_kernel(const float* __restrict__ x,
                          const float* __restrict__ gamma,
                          const float* __restrict__ beta,
                          __half* __restrict__ out) {
    int row = blockIdx.x;
    const float* xr = x + (size_t)row * D_;
    int t = threadIdx.x;
    float4 v = *(const float4*)(xr + t * 4);

    float s = v.x + v.y + v.z + v.w;
    float sq = v.x * v.x + v.y * v.y + v.z * v.z + v.w * v.w;
    #pragma unroll
    for (int o = 16; o > 0; o >>= 1) {
        s  += __shfl_down_sync(0xffffffffu, s,  o);
        sq += __shfl_down_sync(0xffffffffu, sq, o);
    }
    __shared__ float ss[8], sqs[8], stats[2];
    int wid = t >> 5, lane = t & 31;
    if (lane == 0) { ss[wid] = s; sqs[wid] = sq; }
    __syncthreads();
    if (t == 0) {
        float S = 0.f, SQ = 0.f;
        #pragma unroll
        for (int i = 0; i < 8; i++) { S += ss[i]; SQ += sqs[i]; }
        float mu = S / (float)D_;
        float var = SQ / (float)D_ - mu * mu;
        stats[0] = mu;
        stats[1] = rsqrtf(var + EPS_);
    }
    __syncthreads();
    float mu = stats[0], rs = stats[1];

    float4 g4 = *(const float4*)(gamma + t * 4);
    float4 b4 = *(const float4*)(beta + t * 4);
    float4 r;
    r.x = (v.x - mu) * rs * g4.x + b4.x;
    r.y = (v.y - mu) * rs * g4.y + b4.y;
    r.z = (v.z - mu) * rs * g4.z + b4.z;
    r.w = (v.w - mu) * rs * g4.w + b4.w;
    __half2 h0 = __floats2half2_rn(r.x, r.y);
    __half2 h1 = __floats2half2_rn(r.z, r.w);
    *(uint2*)(out + (size_t)row * D_ + t * 4) = make_uint2(*(uint32_t*)&h0, *(uint32_t*)&h1);
}

// ---------------- fp16 mma GEMM: 128x128, BK=64, 3-stage, 512 thr / 16 warps ----------------
// warp tile 32x32 (4m x 4n); 2 CTAs/SM -> 32 warps/SM.
#define AST 72
#define BSTN 136
#define A_STAGE_H (128 * AST)
#define B_STAGE_H (64 * BSTN)
#define STAGE_H (A_STAGE_H + B_STAGE_H)
#define GEMM_SMEM_BYTES (3 * STAGE_H * 2 + 128 * 4)

__global__ __launch_bounds__(512, 2)
void gemm_mma(const __half* __restrict__ A, const __half* __restrict__ W,
              const float* __restrict__ bias, const float* __restrict__ addsrc,
              void* __restrict__ Cout, int M, int N, int K, int flags) {
    extern __shared__ __half smh[];
    float* bias_s = (float*)(smh + 3 * STAGE_H);

    int t = threadIdx.x;
    int wid = t >> 5, lane = t & 31;
    int wm = wid & 3, wn = wid >> 2;       // 4m x 4n, warp tile 32x32
    int gid = lane >> 2, tig = lane & 3;
    int n0 = blockIdx.x * 128, m0 = blockIdx.y * 128;

    uint32_t sA[3], sB[3];
    #pragma unroll
    for (int i = 0; i < 3; i++) {
        sA[i] = smem_u32(smh + i * STAGE_H);
        sB[i] = sA[i] + A_STAGE_H * 2;
    }

    if (t < 32) {
        float4 bv = bias ? *(const float4*)(bias + n0 + t * 4) : make_float4(0.f, 0.f, 0.f, 0.f);
        *(float4*)(bias_s + t * 4) = bv;
    }

    int rsel = lane & 7;
    int t01  = (lane >> 3) & 1;
    int t23  = (lane >> 4) & 1;
    uint32_t aoff[2];
    #pragma unroll
    for (int mf = 0; mf < 2; mf++)
        aoff[mf] = (uint32_t)(((wm * 32 + mf * 16 + t01 * 8 + rsel) * AST + t23 * 8) * 2);
    uint32_t boff[2];
    #pragma unroll
    for (int nf2 = 0; nf2 < 2; nf2++)
        boff[nf2] = (uint32_t)(((t01 * 8 + rsel) * BSTN + wn * 32 + nf2 * 16 + t23 * 8) * 2);

    // loader: A 128x64h (1024 16B chunks, 2/thr), B 64x128h (1024 chunks, 2/thr)
    #define LOAD_TILE(buf, kk0) do { \
        _Pragma("unroll") \
        for (int j = 0; j < 2; j++) { \
            int id = t + j * 512; \
            int row = id >> 3, c4 = id & 7; \
            CP_ASYNC16(sA[buf] + (uint32_t)(row * AST + c4 * 8) * 2u, \
                       A + (size_t)(m0 + row) * K + (kk0) + c4 * 8); \
        } \
        _Pragma("unroll") \
        for (int j = 0; j < 2; j++) { \
            int id = t + j * 512; \
            int row = id >> 4, c = id & 15; \
            CP_ASYNC16(sB[buf] + (uint32_t)(row * BSTN + c * 8) * 2u, \
                       W + (size_t)((kk0) + row) * N + n0 + c * 8); \
        } \
        CP_COMMIT(); \
    } while (0)

    float acc[2][4][4];
    #pragma unroll
    for (int i = 0; i < 2; i++)
        #pragma unroll
        for (int j = 0; j < 4; j++)
            #pragma unroll
            for (int c = 0; c < 4; c++) acc[i][j][c] = 0.f;

    const int NS = K >> 6;
    LOAD_TILE(0, 0);
    LOAD_TILE(1, 64);

    int buf = 0;
    for (int s = 0; s < NS; s++) {
        if (s < NS - 1) { CP_WAIT(1); } else { CP_WAIT(0); }
        __syncthreads();
        if (s + 2 < NS) {
            int nb = (buf + 2 >= 3) ? buf - 1 : buf + 2;
            LOAD_TILE(nb, (s + 2) << 6);
        }

        #pragma unroll
        for (int kk = 0; kk < 4; kk++) {
            uint32_t kaddA = (uint32_t)(kk * 32);
            uint32_t kaddB = (uint32_t)(kk * 16 * BSTN * 2);
            uint32_t af[2][4];
            ldsm_x4(af[0], sA[buf] + aoff[0] + kaddA);
            ldsm_x4(af[1], sA[buf] + aoff[1] + kaddA);
            #pragma unroll
            for (int nf2 = 0; nf2 < 2; nf2++) {
                uint32_t bf[4];
                ldsm_x4_t(bf, sB[buf] + boff[nf2] + kaddB);
                #pragma unroll
                for (int mf = 0; mf < 2; mf++) {
                    mma_f16(acc[mf][nf2 * 2],     af[mf], bf[0], bf[1]);
                    mma_f16(acc[mf][nf2 * 2 + 1], af[mf], bf[2], bf[3]);
                }
            }
        }
        buf = (buf + 1 >= 3) ? 0 : buf + 1;
    }

    bool do_gelu = (flags & 1), out_half = (flags & 4);
    float* Cf = (float*)Cout;
    __half* Ch = (__half*)Cout;
    int row_base = m0 + wm * 32 + gid;
    int colw = wn * 32;
    #pragma unroll
    for (int mf = 0; mf < 2; mf++) {
        #pragma unroll
        for (int rr = 0; rr < 2; rr++) {
            int grow = row_base + mf * 16 + rr * 8;
            size_t roff = (size_t)grow * N + n0 + colw;
            #pragma unroll
            for (int nf = 0; nf < 4; nf++) {
                int cl = colw + nf * 8 + tig * 2;
                float v0 = acc[mf][nf][rr * 2 + 0] + bias_s[cl];
                float v1 = acc[mf][nf][rr * 2 + 1] + bias_s[cl + 1];
                if (do_gelu) {
                    v0 = 0.5f * v0 * (1.f + erff(v0 * 0.70710678118654752f));
                    v1 = 0.5f * v1 * (1.f + erff(v1 * 0.70710678118654752f));
                }
                if (addsrc) {
                    float2 sv = *(const float2*)(addsrc + roff + nf * 8 + tig * 2);
                    v0 += sv.x; v1 += sv.y;
                }
                if (out_half) {
                    __half2 hv = __floats2half2_rn(v0, v1);
                    *(__half2*)(Ch + roff + nf * 8 + tig * 2) = hv;
                } else {
                    *(float2*)(Cf + roff + nf * 8 + tig * 2) = make_float2(v0, v1);
                }
            }
        }
    }
    #undef LOAD_TILE
}

// ---------------- fused attention: FA2-style, base-2 softmax ----------------
#define ST_ 72
#define ATT_SMEM ((128 * ST_ + 4 * 64 * ST_) * 2)

__global__ __launch_bounds__(256)
void attn_mma(const __half* __restrict__ qkv, __half* __restrict__ o) {
    extern __shared__ __half smh[];
    __half* Qs = smh;
    uint32_t uQ = smem_u32(Qs);
    uint32_t uK0 = uQ + 128 * ST_ * 2;
    uint32_t uV0 = uK0 + 2 * 64 * ST_ * 2;
    const uint32_t KVBUF = 64 * ST_ * 2;

    int t = threadIdx.x;
    int w = t >> 5, lane = t & 31;
    int gid = lane >> 2, tig = lane & 3;
    int bh = blockIdx.y;
    int b = bh >> 4, h = bh & 15;
    int q0 = blockIdx.x * 128;
    int qrow = w * 16;
    size_t qbase = ((size_t)b * L_) * D3_ + (size_t)h * DH_;
    size_t obase = ((size_t)b * L_) * D_ + (size_t)h * DH_;

    int rsel = lane & 7;
    int t01  = (lane >> 3) & 1;
    int t23  = (lane >> 4) & 1;
    uint32_t qaoff = (uint32_t)(((qrow + t01 * 8 + rsel) * ST_ + t23 * 8) * 2);
    uint32_t kboff[4], vboff[4];
    #pragma unroll
    for (int nf2 = 0; nf2 < 4; nf2++) {
        kboff[nf2] = (uint32_t)(((nf2 * 16 + t01 * 8 + rsel) * ST_ + t23 * 8) * 2);
        vboff[nf2] = (uint32_t)(((t01 * 8 + rsel) * ST_ + nf2 * 16 + t23 * 8) * 2);
    }

    const __half2 sc2 = __floats2half2_rn(0.125f * LOG2E, 0.125f * LOG2E);
    #pragma unroll
    for (int j = 0; j < 4; j++) {
        int i = t + j * 256;
        int r = i >> 3, c4 = i & 7;
        uint4 v = *(const uint4*)(qkv + qbase + (size_t)(q0 + r) * D3_ + c4 * 8);
        __half2* hp = (__half2*)&v;
        hp[0] = __hmul2(hp[0], sc2); hp[1] = __hmul2(hp[1], sc2);
        hp[2] = __hmul2(hp[2], sc2); hp[3] = __hmul2(hp[3], sc2);
        *(uint4*)(Qs + r * ST_ + c4 * 8) = v;
    }

    #define LOADKV(buf, k0v) do { \
        _Pragma("unroll") \
        for (int j = 0; j < 2; j++) { \
            int id = t + j * 256; \
            int row = id >> 3, c4 = id & 7; \
            uint32_t soff = (uint32_t)(row * ST_ + c4 * 8) * 2u + (buf) * KVBUF; \
            CP_ASYNC16(uK0 + soff, qkv + qbase + 1024 + (size_t)((k0v) + row) * D3_ + c4 * 8); \
            CP_ASYNC16(uV0 + soff, qkv + qbase + 2048 + (size_t)((k0v) + row) * D3_ + c4 * 8); \
        } \
        CP_COMMIT(); \
    } while (0)

    float oacc[8][4];
    #pragma unroll
    for (int i = 0; i < 8; i++)
        #pragma unroll
        for (int j = 0; j < 4; j++) oacc[i][j] = 0.f;
    float m0 = -INFINITY, m1 = -INFINITY, l0 = 0.f, l1 = 0.f;

    LOADKV(0, 0);

    for (int k0 = 0; k0 < L_; k0 += 64) {
        CP_WAIT(0);
        __syncthreads();
        int buf = (k0 >> 6) & 1;
        if (k0 + 64 < L_) LOADKV(buf ^ 1, k0 + 64);
        uint32_t uK = uK0 + buf * KVBUF;
        uint32_t uV = uV0 + buf * KVBUF;

        float sacc[8][4];
        #pragma unroll
        for (int i = 0; i < 8; i++)
            #pragma unroll
            for (int j = 0; j < 4; j++) sacc[i][j] = 0.f;
        #pragma unroll
        for (int kk = 0; kk < 4; kk++) {
            uint32_t kadd = (uint32_t)(kk * 32);
            uint32_t af[4];
            ldsm_x4(af, uQ + qaoff + kadd);
            #pragma unroll
            for (int nf2 = 0; nf2 < 4; nf2++) {
                uint32_t bf[4];
                ldsm_x4(bf, uK + kboff[nf2] + kadd);
                mma_f16(sacc[nf2 * 2],     af, bf[0], bf[2]);
                mma_f16(sacc[nf2 * 2 + 1], af, bf[1], bf[3]);
            }
        }

        float mx0 = -INFINITY, mx1 = -INFINITY;
        #pragma unroll
        for (int nf = 0; nf < 8; nf++) {
            mx0 = fmaxf(mx0, fmaxf(sacc[nf][0], sacc[nf][1]));
            mx1 = fmaxf(mx1, fmaxf(sacc[nf][2], sacc[nf][3]));
        }
        mx0 = fmaxf(mx0, __shfl_xor_sync(0xffffffffu, mx0, 1));
        mx0 = fmaxf(mx0, __shfl_xor_sync(0xffffffffu, mx0, 2));
        mx1 = fmaxf(mx1, __shfl_xor_sync(0xffffffffu, mx1, 1));
        mx1 = fmaxf(mx1, __shfl_xor_sync(0xffffffffu, mx1, 2));
        float mn0 = fmaxf(m0, mx0), mn1 = fmaxf(m1, mx1);
        float al0 = ex2(m0 - mn0), al1 = ex2(m1 - mn1);
        m0 = mn0; m1 = mn1;

        uint32_t ph[8][2];
        float sum0 = 0.f, sum1 = 0.f;
        #pragma unroll
        for (int nf = 0; nf < 8; nf++) {
            float p00 = ex2(sacc[nf][0] - m0);
            float p01 = ex2(sacc[nf][1] - m0);
            float p10 = ex2(sacc[nf][2] - m1);
            float p11 = ex2(sacc[nf][3] - m1);
            sum0 += p00 + p01;
            sum1 += p10 + p11;
            __half2 h0 = __floats2half2_rn(p00, p01);
            __half2 h1 = __floats2half2_rn(p10, p11);
            ph[nf][0] = *(uint32_t*)&h0;
            ph[nf][1] = *(uint32_t*)&h1;
        }
        sum0 += __shfl_xor_sync(0xffffffffu, sum0, 1);
        sum0 += __shfl_xor_sync(0xffffffffu, sum0, 2);
        sum1 += __shfl_xor_sync(0xffffffffu, sum1, 1);
        sum1 += __shfl_xor_sync(0xffffffffu, sum1, 2);
        l0 = l0 * al0 + sum0;
        l1 = l1 * al1 + sum1;

        #pragma unroll
        for (int nf = 0; nf < 8; nf++) {
            oacc[nf][0] *= al0; oacc[nf][1] *= al0;
            oacc[nf][2] *= al1; oacc[nf][3] *= al1;
        }

        #pragma unroll
        for (int kk = 0; kk < 4; kk++) {
            uint32_t af[4] = { ph[2 * kk][0], ph[2 * kk][1], ph[2 * kk + 1][0], ph[2 * kk + 1][1] };
            uint32_t kaddv = (uint32_t)(kk * 16 * ST_ * 2);
            #pragma unroll
            for (int nf2 = 0; nf2 < 4; nf2++) {
                uint32_t bf[4];
                ldsm_x4_t(bf, uV + vboff[nf2] + kaddv);
                mma_f16(oacc[nf2 * 2],     af, bf[0], bf[1]);
                mma_f16(oacc[nf2 * 2 + 1], af, bf[2], bf[3]);
            }
        }
    }

    float inv0 = 1.f / l0, inv1 = 1.f / l1;
    size_t r0off = obase + (size_t)(q0 + qrow + gid) * D_;
    size_t r1off = obase + (size_t)(q0 + qrow + gid + 8) * D_;
    #pragma unroll
    for (int nf = 0; nf < 8; nf++) {
        int c = nf * 8 + tig * 2;
        *(__half2*)(o + r0off + c) = __floats2half2_rn(oacc[nf][0] * inv0, oacc[nf][1] * inv0);
        *(__half2*)(o + r1off + c) = __floats2half2_rn(oacc[nf][2] * inv1, oacc[nf][3] * inv1);
    }
    #undef LOADKV
}

// ---------------- launch ----------------
extern "C" void kernel_launch(void* const* d_in, const int* in_sizes, int n_in,
                              void* d_out, int out_size) {
    const float* x     = (const float*)d_in[0];
    const float* pos   = (const float*)d_in[1];
    const float* ln1_g = (const float*)d_in[2];
    const float* ln1_b = (const float*)d_in[3];
    const float* Wq    = (const float*)d_in[4];
    const float* Wk    = (const float*)d_in[5];
    const float* Wv    = (const float*)d_in[6];
    const float* Wo    = (const float*)d_in[7];
    const float* bo    = (const float*)d_in[8];
    const float* ln2_g = (const float*)d_in[9];
    const float* ln2_b = (const float*)d_in[10];
    const float* W1    = (const float*)d_in[11];
    const float* b1    = (const float*)d_in[12];
    const float* W2    = (const float*)d_in[13];
    const float* b2    = (const float*)d_in[14];
    float* out = (float*)d_out;

    __half *h, *qkv, *ao, *ff, *wqkv, *woh, *w1h, *w2h;
    float *x2;
    cudaGetSymbolAddress((void**)&h,    g_h);
    cudaGetSymbolAddress((void**)&qkv,  g_qkv);
    cudaGetSymbolAddress((void**)&ao,   g_ao);
    cudaGetSymbolAddress((void**)&x2,   g_x2);
    cudaGetSymbolAddress((void**)&ff,   g_ff);
    cudaGetSymbolAddress((void**)&wqkv, g_wqkv);
    cudaGetSymbolAddress((void**)&woh,  g_woh);
    cudaGetSymbolAddress((void**)&w1h,  g_w1h);
    cudaGetSymbolAddress((void**)&w2h,  g_w2h);

    cudaFuncSetAttribute(gemm_mma, cudaFuncAttributeMaxDynamicSharedMemorySize, GEMM_SMEM_BYTES);
    cudaFuncSetAttribute(attn_mma, cudaFuncAttributeMaxDynamicSharedMemorySize, ATT_SMEM);

    const int ROWS = B_ * L_;   // 4096

    // 0+1) fused: h = fp16(LN1(x) + pos)  AND  all weight converts
    prep_kernel<<<ROWS + 12288, 256>>>(x, ln1_g, ln1_b, pos, h,
                                       Wq, Wk, Wv, Wo, W1, W2,
                                       wqkv, woh, w1h, w2h);

    // 2) fused qkv = h @ [Wq|Wk|Wv]  (half out)
    {
        dim3 grid(D3_ / 128, ROWS / 128);
        gemm_mma<<<grid, 512, GEMM_SMEM_BYTES>>>(h, wqkv, nullptr, nullptr, qkv, ROWS, D3_, D_, 4);
    }

    // 3) attention -> ao (half)
    {
        dim3 grid(L_ / 128, B_ * H_);
        attn_mma<<<grid, 256, ATT_SMEM>>>(qkv, ao);
    }

    // 4) x2 = x + ao @ Wo + bo  (float out, exact residual)
    {
        dim3 grid(D_ / 128, ROWS / 128);
        gemm_mma<<<grid, 512, GEMM_SMEM_BYTES>>>(ao, woh, bo, x, x2, ROWS, D_, D_, 0);
    }

    // 5) h = fp16(LN2(x2))
    ln_kernel<<<ROWS, 256>>>(x2, ln2_g, ln2_b, h);

    // 6) ff = fp16(gelu(h @ W1 + b1))
    {
        dim3 grid(FF_ / 128, ROWS / 128);
        gemm_mma<<<grid, 512, GEMM_SMEM_BYTES>>>(h, w1h, b1, nullptr, ff, ROWS, FF_, D_, 5);
    }

    // 7) out = x2 + ff @ W2 + b2  (float out)
    {
        dim3 grid(D_ / 128, ROWS / 128);
        gemm_mma<<<grid, 512, GEMM_SMEM_BYTES>>>(ff, w2h, b2, x2, out, ROWS, D_, FF_, 0);
    }
}

// round 16
// speedup vs baseline: 1.0177x; 1.0177x over previous
#include <cuda_runtime.h>
#include <cuda_fp16.h>
#include <math.h>
#include <stdint.h>

#define B_ 2
#define L_ 2048
#define D_ 1024
#define H_ 16
#define DH_ 64
#define FF_ 4096
#define EPS_ 1e-5f
#define D3_ 3072
#define LOG2E 1.4426950408889634f

// ---------------- scratch (device globals) ----------------
__device__ __half g_h[B_ * L_ * D_];
__device__ __half g_qkv[B_ * L_ * D3_];
__device__ __half g_ao[B_ * L_ * D_];
__device__ float  g_x2[B_ * L_ * D_];
__device__ __half g_ff[B_ * L_ * FF_];
__device__ __half g_wqkv[D_ * D3_];    // [1024][3072] N-major
__device__ __half g_woh[D_ * D_];
__device__ __half g_w1h[D_ * FF_];
__device__ __half g_w2h[FF_ * D_];

// ---------------- helpers ----------------
__device__ __forceinline__ uint32_t smem_u32(const void* p) {
    uint32_t a;
    asm("{ .reg .u64 t; cvta.to.shared.u64 t, %1; cvt.u32.u64 %0, t; }" : "=r"(a) : "l"(p));
    return a;
}
__device__ __forceinline__ void mma_f16(float* c, const uint32_t* a, uint32_t b0, uint32_t b1) {
    asm volatile(
        "mma.sync.aligned.m16n8k16.row.col.f32.f16.f16.f32 "
        "{%0,%1,%2,%3}, {%4,%5,%6,%7}, {%8,%9}, {%0,%1,%2,%3};"
        : "+f"(c[0]), "+f"(c[1]), "+f"(c[2]), "+f"(c[3])
        : "r"(a[0]), "r"(a[1]), "r"(a[2]), "r"(a[3]), "r"(b0), "r"(b1));
}
__device__ __forceinline__ void ldsm_x4(uint32_t* r, uint32_t addr) {
    asm volatile("ldmatrix.sync.aligned.m8n8.x4.shared.b16 {%0,%1,%2,%3}, [%4];"
        : "=r"(r[0]), "=r"(r[1]), "=r"(r[2]), "=r"(r[3]) : "r"(addr));
}
__device__ __forceinline__ void ldsm_x4_t(uint32_t* r, uint32_t addr) {
    asm volatile("ldmatrix.sync.aligned.m8n8.x4.trans.shared.b16 {%0,%1,%2,%3}, [%4];"
        : "=r"(r[0]), "=r"(r[1]), "=r"(r[2]), "=r"(r[3]) : "r"(addr));
}
__device__ __forceinline__ float ex2(float x) {
    float r;
    asm("ex2.approx.f32 %0, %1;" : "=f"(r) : "f"(x));
    return r;
}

#define CP_ASYNC16(dst, src) \
    asm volatile("cp.async.cg.shared.global [%0], [%1], 16;" :: "r"(dst), "l"(src))
#define CP_COMMIT() asm volatile("cp.async.commit_group;" ::: "memory")
#define CP_WAIT(n)  asm volatile("cp.async.wait_group %0;" :: "n"(n) : "memory")

// ---------------- fused prep: LN1(+pos) AND weight convert in one launch ----------------
__global__ void prep_kernel(const float* __restrict__ x,
                            const float* __restrict__ gamma,
                            const float* __restrict__ beta,
                            const float* __restrict__ pos,
                            __half* __restrict__ out,
                            const float* __restrict__ Wq, const float* __restrict__ Wk,
                            const float* __restrict__ Wv, const float* __restrict__ Wo,
                            const float* __restrict__ W1, const float* __restrict__ W2,
                            __half* __restrict__ wqkv, __half* __restrict__ woh,
                            __half* __restrict__ w1h, __half* __restrict__ w2h) {
    int t = threadIdx.x;
    if (blockIdx.x < (unsigned)(B_ * L_)) {
        int row = blockIdx.x;
        int l = row & (L_ - 1);
        const float* xr = x + (size_t)row * D_;
        float4 v = *(const float4*)(xr + t * 4);

        float s = v.x + v.y + v.z + v.w;
        float sq = v.x * v.x + v.y * v.y + v.z * v.z + v.w * v.w;
        #pragma unroll
        for (int o = 16; o > 0; o >>= 1) {
            s  += __shfl_down_sync(0xffffffffu, s,  o);
            sq += __shfl_down_sync(0xffffffffu, sq, o);
        }
        __shared__ float ss[8], sqs[8], stats[2];
        int wid = t >> 5, lane = t & 31;
        if (lane == 0) { ss[wid] = s; sqs[wid] = sq; }
        __syncthreads();
        if (t == 0) {
            float S = 0.f, SQ = 0.f;
            #pragma unroll
            for (int i = 0; i < 8; i++) { S += ss[i]; SQ += sqs[i]; }
            float mu = S / (float)D_;
            float var = SQ / (float)D_ - mu * mu;
            stats[0] = mu;
            stats[1] = rsqrtf(var + EPS_);
        }
        __syncthreads();
        float mu = stats[0], rs = stats[1];

        float4 g4 = *(const float4*)(gamma + t * 4);
        float4 b4 = *(const float4*)(beta + t * 4);
        float4 r;
        r.x = (v.x - mu) * rs * g4.x + b4.x;
        r.y = (v.y - mu) * rs * g4.y + b4.y;
        r.z = (v.z - mu) * rs * g4.z + b4.z;
        r.w = (v.w - mu) * rs * g4.w + b4.w;
        float4 p4 = *(const float4*)(pos + (size_t)l * D_ + t * 4);
        r.x += p4.x; r.y += p4.y; r.z += p4.z; r.w += p4.w;
        __half2 h0 = __floats2half2_rn(r.x, r.y);
        __half2 h1 = __floats2half2_rn(r.z, r.w);
        *(uint2*)(out + (size_t)row * D_ + t * 4) = make_uint2(*(uint32_t*)&h0, *(uint32_t*)&h1);
    } else {
        const int M1 = 1 << 20;
        size_t i = ((size_t)(blockIdx.x - B_ * L_) * 256 + t) * 4;
        const float* src;
        __half* dst;
        size_t soff, doff;
        if (i < (size_t)3 * M1) {
            int which = (int)(i >> 20);
            size_t li = i & (M1 - 1);
            int k = (int)(li >> 10), n = (int)(li & 1023);
            src = (which == 0) ? Wq : (which == 1) ? Wk : Wv;
            soff = li;
            dst = wqkv;
            doff = (size_t)k * D3_ + which * 1024 + n;
        } else if (i < (size_t)4 * M1) {
            src = Wo; soff = i - 3 * M1; dst = woh; doff = soff;
        } else if (i < (size_t)8 * M1) {
            src = W1; soff = i - 4 * M1; dst = w1h; doff = soff;
        } else {
            src = W2; soff = i - (size_t)8 * M1; dst = w2h; doff = soff;
        }
        float4 v = *(const float4*)(src + soff);
        __half2 h0 = __floats2half2_rn(v.x, v.y);
        __half2 h1 = __floats2half2_rn(v.z, v.w);
        *(uint2*)(dst + doff) = make_uint2(*(uint32_t*)&h0, *(uint32_t*)&h1);
    }
}

// ---------------- LayerNorm (standalone, for LN2), output fp16 ----------------
__global__ void ln_kernel(const float* __restrict__ x,
                          const float* __restrict__ gamma,
                          const float* __restrict__ beta,
                          __half* __restrict__ out) {
    int row = blockIdx.x;
    const float* xr = x + (size_t)row * D_;
    int t = threadIdx.x;
    float4 v = *(const float4*)(xr + t * 4);

    float s = v.x + v.y + v.z + v.w;
    float sq = v.x * v.x + v.y * v.y + v.z * v.z + v.w * v.w;
    #pragma unroll
    for (int o = 16; o > 0; o >>= 1) {
        s  += __shfl_down_sync(0xffffffffu, s,  o);
        sq += __shfl_down_sync(0xffffffffu, sq, o);
    }
    __shared__ float ss[8], sqs[8], stats[2];
    int wid = t >> 5, lane = t & 31;
    if (lane == 0) { ss[wid] = s; sqs[wid] = sq; }
    __syncthreads();
    if (t == 0) {
        float S = 0.f, SQ = 0.f;
        #pragma unroll
        for (int i = 0; i < 8; i++) { S += ss[i]; SQ += sqs[i]; }
        float mu = S / (float)D_;
        float var = SQ / (float)D_ - mu * mu;
        stats[0] = mu;
        stats[1] = rsqrtf(var + EPS_);
    }
    __syncthreads();
    float mu = stats[0], rs = stats[1];

    float4 g4 = *(const float4*)(gamma + t * 4);
    float4 b4 = *(const float4*)(beta + t * 4);
    float4 r;
    r.x = (v.x - mu) * rs * g4.x + b4.x;
    r.y = (v.y - mu) * rs * g4.y + b4.y;
    r.z = (v.z - mu) * rs * g4.z + b4.z;
    r.w = (v.w - mu) * rs * g4.w + b4.w;
    __half2 h0 = __floats2half2_rn(r.x, r.y);
    __half2 h1 = __floats2half2_rn(r.z, r.w);
    *(uint2*)(out + (size_t)row * D_ + t * 4) = make_uint2(*(uint32_t*)&h0, *(uint32_t*)&h1);
}

// ---------------- fp16 mma GEMM: 128x128, BK=64, 3-stage, frag double-buffer ----------------
// (round-14 proven config: 256 threads, 8 warps 2m x 4n, warp tile 64x32)
#define AST 72
#define BSTN 136
#define A_STAGE_H (128 * AST)
#define B_STAGE_H (64 * BSTN)
#define STAGE_H (A_STAGE_H + B_STAGE_H)
#define GEMM_SMEM_BYTES (3 * STAGE_H * 2 + 128 * 4)

__global__ __launch_bounds__(256, 2)
void gemm_mma(const __half* __restrict__ A, const __half* __restrict__ W,
              const float* __restrict__ bias, const float* __restrict__ addsrc,
              void* __restrict__ Cout, int M, int N, int K, int flags) {
    extern __shared__ __half smh[];
    float* bias_s = (float*)(smh + 3 * STAGE_H);

    int t = threadIdx.x;
    int wid = t >> 5, lane = t & 31;
    int wm = wid & 1, wn = wid >> 1;
    int gid = lane >> 2, tig = lane & 3;
    int n0 = blockIdx.x * 128, m0 = blockIdx.y * 128;

    uint32_t sA[3], sB[3];
    #pragma unroll
    for (int i = 0; i < 3; i++) {
        sA[i] = smem_u32(smh + i * STAGE_H);
        sB[i] = sA[i] + A_STAGE_H * 2;
    }

    if (t < 32) {
        float4 bv = bias ? *(const float4*)(bias + n0 + t * 4) : make_float4(0.f, 0.f, 0.f, 0.f);
        *(float4*)(bias_s + t * 4) = bv;
    }

    int rsel = lane & 7;
    int t01  = (lane >> 3) & 1;
    int t23  = (lane >> 4) & 1;
    uint32_t aoff[4];
    #pragma unroll
    for (int mf = 0; mf < 4; mf++)
        aoff[mf] = (uint32_t)(((wm * 64 + mf * 16 + t01 * 8 + rsel) * AST + t23 * 8) * 2);
    uint32_t boff[2];
    #pragma unroll
    for (int nf2 = 0; nf2 < 2; nf2++)
        boff[nf2] = (uint32_t)(((t01 * 8 + rsel) * BSTN + wn * 32 + nf2 * 16 + t23 * 8) * 2);

    #define LOAD_TILE(buf, kk0) do { \
        _Pragma("unroll") \
        for (int j = 0; j < 4; j++) { \
            int id = t + j * 256; \
            int row = id >> 3, c4 = id & 7; \
            CP_ASYNC16(sA[buf] + (uint32_t)(row * AST + c4 * 8) * 2u, \
                       A + (size_t)(m0 + row) * K + (kk0) + c4 * 8); \
        } \
        _Pragma("unroll") \
        for (int j = 0; j < 4; j++) { \
            int id = t + j * 256; \
            int row = id >> 4, c = id & 15; \
            CP_ASYNC16(sB[buf] + (uint32_t)(row * BSTN + c * 8) * 2u, \
                       W + (size_t)((kk0) + row) * N + n0 + c * 8); \
        } \
        CP_COMMIT(); \
    } while (0)

    #define LDFRAG(dstA, dstB, sbuf, kk) do { \
        uint32_t _kaddA = (uint32_t)((kk) * 32); \
        uint32_t _kaddB = (uint32_t)((kk) * 16 * BSTN * 2); \
        _Pragma("unroll") \
        for (int mf = 0; mf < 4; mf++) \
            ldsm_x4((dstA)[mf], sA[sbuf] + aoff[mf] + _kaddA); \
        ldsm_x4_t((dstB)[0], sB[sbuf] + boff[0] + _kaddB); \
        ldsm_x4_t((dstB)[1], sB[sbuf] + boff[1] + _kaddB); \
    } while (0)

    float acc[4][4][4];
    #pragma unroll
    for (int i = 0; i < 4; i++)
        #pragma unroll
        for (int j = 0; j < 4; j++)
            #pragma unroll
            for (int c = 0; c < 4; c++) acc[i][j][c] = 0.f;

    const int NS = K >> 6;
    LOAD_TILE(0, 0);
    LOAD_TILE(1, 64);

    uint32_t afr[2][4][4];
    uint32_t bfr[2][2][4];

    int buf = 0;
    for (int s = 0; s < NS; s++) {
        if (s < NS - 1) { CP_WAIT(1); } else { CP_WAIT(0); }
        __syncthreads();
        if (s + 2 < NS) {
            int nb = (buf + 2 >= 3) ? buf - 1 : buf + 2;
            LOAD_TILE(nb, (s + 2) << 6);
        }

        LDFRAG(afr[0], bfr[0], buf, 0);

        #pragma unroll
        for (int kk = 0; kk < 4; kk++) {
            int cur = kk & 1, nxt = cur ^ 1;
            if (kk < 3) LDFRAG(afr[nxt], bfr[nxt], buf, kk + 1);
            #pragma unroll
            for (int nf2 = 0; nf2 < 2; nf2++) {
                #pragma unroll
                for (int mf = 0; mf < 4; mf++) {
                    mma_f16(acc[mf][nf2 * 2],     afr[cur][mf], bfr[cur][nf2][0], bfr[cur][nf2][1]);
                    mma_f16(acc[mf][nf2 * 2 + 1], afr[cur][mf], bfr[cur][nf2][2], bfr[cur][nf2][3]);
                }
            }
        }
        buf = (buf + 1 >= 3) ? 0 : buf + 1;
    }

    bool do_gelu = (flags & 1), out_half = (flags & 4);
    float* Cf = (float*)Cout;
    __half* Ch = (__half*)Cout;
    int row_base = m0 + wm * 64 + gid;
    int colw = wn * 32;
    #pragma unroll
    for (int mf = 0; mf < 4; mf++) {
        #pragma unroll
        for (int rr = 0; rr < 2; rr++) {
            int grow = row_base + mf * 16 + rr * 8;
            size_t roff = (size_t)grow * N + n0 + colw;
            #pragma unroll
            for (int nf = 0; nf < 4; nf++) {
                int cl = colw + nf * 8 + tig * 2;
                float v0 = acc[mf][nf][rr * 2 + 0] + bias_s[cl];
                float v1 = acc[mf][nf][rr * 2 + 1] + bias_s[cl + 1];
                if (do_gelu) {
                    v0 = 0.5f * v0 * (1.f + erff(v0 * 0.70710678118654752f));
                    v1 = 0.5f * v1 * (1.f + erff(v1 * 0.70710678118654752f));
                }
                if (addsrc) {
                    float2 sv = *(const float2*)(addsrc + roff + nf * 8 + tig * 2);
                    v0 += sv.x; v1 += sv.y;
                }
                if (out_half) {
                    __half2 hv = __floats2half2_rn(v0, v1);
                    *(__half2*)(Ch + roff + nf * 8 + tig * 2) = hv;
                } else {
                    *(float2*)(Cf + roff + nf * 8 + tig * 2) = make_float2(v0, v1);
                }
            }
        }
    }
    #undef LOAD_TILE
    #undef LDFRAG
}

// ---------------- fused attention: FA2-style, base-2 softmax, Q frags hoisted ----------------
#define ST_ 72
#define ATT_SMEM ((128 * ST_ + 4 * 64 * ST_) * 2)

__global__ __launch_bounds__(256)
void attn_mma(const __half* __restrict__ qkv, __half* __restrict__ o) {
    extern __shared__ __half smh[];
    __half* Qs = smh;
    uint32_t uQ = smem_u32(Qs);
    uint32_t uK0 = uQ + 128 * ST_ * 2;
    uint32_t uV0 = uK0 + 2 * 64 * ST_ * 2;
    const uint32_t KVBUF = 64 * ST_ * 2;

    int t = threadIdx.x;
    int w = t >> 5, lane = t & 31;
    int gid = lane >> 2, tig = lane & 3;
    int bh = blockIdx.y;
    int b = bh >> 4, h = bh & 15;
    int q0 = blockIdx.x * 128;
    int qrow = w * 16;
    size_t qbase = ((size_t)b * L_) * D3_ + (size_t)h * DH_;
    size_t obase = ((size_t)b * L_) * D_ + (size_t)h * DH_;

    int rsel = lane & 7;
    int t01  = (lane >> 3) & 1;
    int t23  = (lane >> 4) & 1;
    uint32_t qaoff = (uint32_t)(((qrow + t01 * 8 + rsel) * ST_ + t23 * 8) * 2);
    uint32_t kboff[4], vboff[4];
    #pragma unroll
    for (int nf2 = 0; nf2 < 4; nf2++) {
        kboff[nf2] = (uint32_t)(((nf2 * 16 + t01 * 8 + rsel) * ST_ + t23 * 8) * 2);
        vboff[nf2] = (uint32_t)(((t01 * 8 + rsel) * ST_ + nf2 * 16 + t23 * 8) * 2);
    }

    const __half2 sc2 = __floats2half2_rn(0.125f * LOG2E, 0.125f * LOG2E);
    #pragma unroll
    for (int j = 0; j < 4; j++) {
        int i = t + j * 256;
        int r = i >> 3, c4 = i & 7;
        uint4 v = *(const uint4*)(qkv + qbase + (size_t)(q0 + r) * D3_ + c4 * 8);
        __half2* hp = (__half2*)&v;
        hp[0] = __hmul2(hp[0], sc2); hp[1] = __hmul2(hp[1], sc2);
        hp[2] = __hmul2(hp[2], sc2); hp[3] = __hmul2(hp[3], sc2);
        *(uint4*)(Qs + r * ST_ + c4 * 8) = v;
    }

    #define LOADKV(buf, k0v) do { \
        _Pragma("unroll") \
        for (int j = 0; j < 2; j++) { \
            int id = t + j * 256; \
            int row = id >> 3, c4 = id & 7; \
            uint32_t soff = (uint32_t)(row * ST_ + c4 * 8) * 2u + (buf) * KVBUF; \
            CP_ASYNC16(uK0 + soff, qkv + qbase + 1024 + (size_t)((k0v) + row) * D3_ + c4 * 8); \
            CP_ASYNC16(uV0 + soff, qkv + qbase + 2048 + (size_t)((k0v) + row) * D3_ + c4 * 8); \
        } \
        CP_COMMIT(); \
    } while (0)

    LOADKV(0, 0);

    // hoist Q fragments to registers (loop-invariant over all k-tiles)
    __syncthreads();
    uint32_t qfr[4][4];
    #pragma unroll
    for (int kk = 0; kk < 4; kk++)
        ldsm_x4(qfr[kk], uQ + qaoff + (uint32_t)(kk * 32));

    float oacc[8][4];
    #pragma unroll
    for (int i = 0; i < 8; i++)
        #pragma unroll
        for (int j = 0; j < 4; j++) oacc[i][j] = 0.f;
    float m0 = -INFINITY, m1 = -INFINITY, l0 = 0.f, l1 = 0.f;

    for (int k0 = 0; k0 < L_; k0 += 64) {
        CP_WAIT(0);
        __syncthreads();
        int buf = (k0 >> 6) & 1;
        if (k0 + 64 < L_) LOADKV(buf ^ 1, k0 + 64);
        uint32_t uK = uK0 + buf * KVBUF;
        uint32_t uV = uV0 + buf * KVBUF;

        float sacc[8][4];
        #pragma unroll
        for (int i = 0; i < 8; i++)
            #pragma unroll
            for (int j = 0; j < 4; j++) sacc[i][j] = 0.f;
        #pragma unroll
        for (int kk = 0; kk < 4; kk++) {
            #pragma unroll
            for (int nf2 = 0; nf2 < 4; nf2++) {
                uint32_t bf[4];
                ldsm_x4(bf, uK + kboff[nf2] + (uint32_t)(kk * 32));
                mma_f16(sacc[nf2 * 2],     qfr[kk], bf[0], bf[2]);
                mma_f16(sacc[nf2 * 2 + 1], qfr[kk], bf[1], bf[3]);
            }
        }

        float mx0 = -INFINITY, mx1 = -INFINITY;
        #pragma unroll
        for (int nf = 0; nf < 8; nf++) {
            mx0 = fmaxf(mx0, fmaxf(sacc[nf][0], sacc[nf][1]));
            mx1 = fmaxf(mx1, fmaxf(sacc[nf][2], sacc[nf][3]));
        }
        mx0 = fmaxf(mx0, __shfl_xor_sync(0xffffffffu, mx0, 1));
        mx0 = fmaxf(mx0, __shfl_xor_sync(0xffffffffu, mx0, 2));
        mx1 = fmaxf(mx1, __shfl_xor_sync(0xffffffffu, mx1, 1));
        mx1 = fmaxf(mx1, __shfl_xor_sync(0xffffffffu, mx1, 2));
        float mn0 = fmaxf(m0, mx0), mn1 = fmaxf(m1, mx1);
        float al0 = ex2(m0 - mn0), al1 = ex2(m1 - mn1);
        m0 = mn0; m1 = mn1;

        uint32_t ph[8][2];
        float sum0 = 0.f, sum1 = 0.f;
        #pragma unroll
        for (int nf = 0; nf < 8; nf++) {
            float p00 = ex2(sacc[nf][0] - m0);
            float p01 = ex2(sacc[nf][1] - m0);
            float p10 = ex2(sacc[nf][2] - m1);
            float p11 = ex2(sacc[nf][3] - m1);
            sum0 += p00 + p01;
            sum1 += p10 + p11;
            __half2 h0 = __floats2half2_rn(p00, p01);
            __half2 h1 = __floats2half2_rn(p10, p11);
            ph[nf][0] = *(uint32_t*)&h0;
            ph[nf][1] = *(uint32_t*)&h1;
        }
        sum0 += __shfl_xor_sync(0xffffffffu, sum0, 1);
        sum0 += __shfl_xor_sync(0xffffffffu, sum0, 2);
        sum1 += __shfl_xor_sync(0xffffffffu, sum1, 1);
        sum1 += __shfl_xor_sync(0xffffffffu, sum1, 2);
        l0 = l0 * al0 + sum0;
        l1 = l1 * al1 + sum1;

        #pragma unroll
        for (int nf = 0; nf < 8; nf++) {
            oacc[nf][0] *= al0; oacc[nf][1] *= al0;
            oacc[nf][2] *= al1; oacc[nf][3] *= al1;
        }

        #pragma unroll
        for (int kk = 0; kk < 4; kk++) {
            uint32_t af[4] = { ph[2 * kk][0], ph[2 * kk][1], ph[2 * kk + 1][0], ph[2 * kk + 1][1] };
            uint32_t kaddv = (uint32_t)(kk * 16 * ST_ * 2);
            #pragma unroll
            for (int nf2 = 0; nf2 < 4; nf2++) {
                uint32_t bf[4];
                ldsm_x4_t(bf, uV + vboff[nf2] + kaddv);
                mma_f16(oacc[nf2 * 2],     af, bf[0], bf[1]);
                mma_f16(oacc[nf2 * 2 + 1], af, bf[2], bf[3]);
            }
        }
    }

    float inv0 = 1.f / l0, inv1 = 1.f / l1;
    size_t r0off = obase + (size_t)(q0 + qrow + gid) * D_;
    size_t r1off = obase + (size_t)(q0 + qrow + gid + 8) * D_;
    #pragma unroll
    for (int nf = 0; nf < 8; nf++) {
        int c = nf * 8 + tig * 2;
        *(__half2*)(o + r0off + c) = __floats2half2_rn(oacc[nf][0] * inv0, oacc[nf][1] * inv0);
        *(__half2*)(o + r1off + c) = __floats2half2_rn(oacc[nf][2] * inv1, oacc[nf][3] * inv1);
    }
    #undef LOADKV
}

// ---------------- launch ----------------
extern "C" void kernel_launch(void* const* d_in, const int* in_sizes, int n_in,
                              void* d_out, int out_size) {
    const float* x     = (const float*)d_in[0];
    const float* pos   = (const float*)d_in[1];
    const float* ln1_g = (const float*)d_in[2];
    const float* ln1_b = (const float*)d_in[3];
    const float* Wq    = (const float*)d_in[4];
    const float* Wk    = (const float*)d_in[5];
    const float* Wv    = (const float*)d_in[6];
    const float* Wo    = (const float*)d_in[7];
    const float* bo    = (const float*)d_in[8];
    const float* ln2_g = (const float*)d_in[9];
    const float* ln2_b = (const float*)d_in[10];
    const float* W1    = (const float*)d_in[11];
    const float* b1    = (const float*)d_in[12];
    const float* W2    = (const float*)d_in[13];
    const float* b2    = (const float*)d_in[14];
    float* out = (float*)d_out;

    __half *h, *qkv, *ao, *ff, *wqkv, *woh, *w1h, *w2h;
    float *x2;
    cudaGetSymbolAddress((void**)&h,    g_h);
    cudaGetSymbolAddress((void**)&qkv,  g_qkv);
    cudaGetSymbolAddress((void**)&ao,   g_ao);
    cudaGetSymbolAddress((void**)&x2,   g_x2);
    cudaGetSymbolAddress((void**)&ff,   g_ff);
    cudaGetSymbolAddress((void**)&wqkv, g_wqkv);
    cudaGetSymbolAddress((void**)&woh,  g_woh);
    cudaGetSymbolAddress((void**)&w1h,  g_w1h);
    cudaGetSymbolAddress((void**)&w2h,  g_w2h);

    cudaFuncSetAttribute(gemm_mma, cudaFuncAttributeMaxDynamicSharedMemorySize, GEMM_SMEM_BYTES);
    cudaFuncSetAttribute(attn_mma, cudaFuncAttributeMaxDynamicSharedMemorySize, ATT_SMEM);

    const int ROWS = B_ * L_;   // 4096

    // 0+1) fused: h = fp16(LN1(x) + pos)  AND  all weight converts
    prep_kernel<<<ROWS + 12288, 256>>>(x, ln1_g, ln1_b, pos, h,
                                       Wq, Wk, Wv, Wo, W1, W2,
                                       wqkv, woh, w1h, w2h);

    // 2) fused qkv = h @ [Wq|Wk|Wv]  (half out)
    {
        dim3 grid(D3_ / 128, ROWS / 128);
        gemm_mma<<<grid, 256, GEMM_SMEM_BYTES>>>(h, wqkv, nullptr, nullptr, qkv, ROWS, D3_, D_, 4);
    }

    // 3) attention -> ao (half)
    {
        dim3 grid(L_ / 128, B_ * H_);
        attn_mma<<<grid, 256, ATT_SMEM>>>(qkv, ao);
    }

    // 4) x2 = x + ao @ Wo + bo  (float out, exact residual)
    {
        dim3 grid(D_ / 128, ROWS / 128);
        gemm_mma<<<grid, 256, GEMM_SMEM_BYTES>>>(ao, woh, bo, x, x2, ROWS, D_, D_, 0);
    }

    // 5) h = fp16(LN2(x2))
    ln_kernel<<<ROWS, 256>>>(x2, ln2_g, ln2_b, h);

    // 6) ff = fp16(gelu(h @ W1 + b1))
    {
        dim3 grid(FF_ / 128, ROWS / 128);
        gemm_mma<<<grid, 256, GEMM_SMEM_BYTES>>>(h, w1h, b1, nullptr, ff, ROWS, FF_, D_, 5);
    }

    // 7) out = x2 + ff @ W2 + b2  (float out)
    {
        dim3 grid(D_ / 128, ROWS / 128);
        gemm_mma<<<grid, 256, GEMM_SMEM_BYTES>>>(ff, w2h, b2, x2, out, ROWS, D_, FF_, 0);
    }
}

// round 17
// speedup vs baseline: 1.0396x; 1.0215x over previous
#include <cuda_runtime.h>
#include <cuda_fp16.h>
#include <math.h>
#include <stdint.h>

#define B_ 2
#define L_ 2048
#define D_ 1024
#define H_ 16
#define DH_ 64
#define FF_ 4096
#define EPS_ 1e-5f
#define D3_ 3072
#define LOG2E 1.4426950408889634f

// ---------------- scratch (device globals) ----------------
__device__ __half g_h[B_ * L_ * D_];
__device__ __half g_qkv[B_ * L_ * D3_];
__device__ __half g_ao[B_ * L_ * D_];
__device__ float  g_x2[B_ * L_ * D_];
__device__ __half g_ff[B_ * L_ * FF_];
__device__ __half g_wqkv[D_ * D3_];    // [1024][3072] N-major
__device__ __half g_woh[D_ * D_];
__device__ __half g_w1h[D_ * FF_];
__device__ __half g_w2h[FF_ * D_];

// ---------------- helpers ----------------
__device__ __forceinline__ uint32_t smem_u32(const void* p) {
    uint32_t a;
    asm("{ .reg .u64 t; cvta.to.shared.u64 t, %1; cvt.u32.u64 %0, t; }" : "=r"(a) : "l"(p));
    return a;
}
__device__ __forceinline__ void mma_f16(float* c, const uint32_t* a, uint32_t b0, uint32_t b1) {
    asm volatile(
        "mma.sync.aligned.m16n8k16.row.col.f32.f16.f16.f32 "
        "{%0,%1,%2,%3}, {%4,%5,%6,%7}, {%8,%9}, {%0,%1,%2,%3};"
        : "+f"(c[0]), "+f"(c[1]), "+f"(c[2]), "+f"(c[3])
        : "r"(a[0]), "r"(a[1]), "r"(a[2]), "r"(a[3]), "r"(b0), "r"(b1));
}
__device__ __forceinline__ void ldsm_x4(uint32_t* r, uint32_t addr) {
    asm volatile("ldmatrix.sync.aligned.m8n8.x4.shared.b16 {%0,%1,%2,%3}, [%4];"
        : "=r"(r[0]), "=r"(r[1]), "=r"(r[2]), "=r"(r[3]) : "r"(addr));
}
__device__ __forceinline__ void ldsm_x4_t(uint32_t* r, uint32_t addr) {
    asm volatile("ldmatrix.sync.aligned.m8n8.x4.trans.shared.b16 {%0,%1,%2,%3}, [%4];"
        : "=r"(r[0]), "=r"(r[1]), "=r"(r[2]), "=r"(r[3]) : "r"(addr));
}
__device__ __forceinline__ float ex2(float x) {
    float r;
    asm("ex2.approx.f32 %0, %1;" : "=f"(r) : "f"(x));
    return r;
}

#define CP_ASYNC16(dst, src) \
    asm volatile("cp.async.cg.shared.global [%0], [%1], 16;" :: "r"(dst), "l"(src))
#define CP_COMMIT() asm volatile("cp.async.commit_group;" ::: "memory")
#define CP_WAIT(n)  asm volatile("cp.async.wait_group %0;" :: "n"(n) : "memory")

// ---------------- fused prep: LN1(+pos) AND qkv-weight interleave convert ----------------
// blocks [0, 4096): LayerNorm rows.  blocks [4096, 7168): Wq|Wk|Wv fp32->fp16 interleave.
__global__ void prep_kernel(const float* __restrict__ x,
                            const float* __restrict__ gamma,
                            const float* __restrict__ beta,
                            const float* __restrict__ pos,
                            __half* __restrict__ out,
                            const float* __restrict__ Wq, const float* __restrict__ Wk,
                            const float* __restrict__ Wv,
                            __half* __restrict__ wqkv) {
    int t = threadIdx.x;
    if (blockIdx.x < (unsigned)(B_ * L_)) {
        int row = blockIdx.x;
        int l = row & (L_ - 1);
        const float* xr = x + (size_t)row * D_;
        float4 v = *(const float4*)(xr + t * 4);

        float s = v.x + v.y + v.z + v.w;
        float sq = v.x * v.x + v.y * v.y + v.z * v.z + v.w * v.w;
        #pragma unroll
        for (int o = 16; o > 0; o >>= 1) {
            s  += __shfl_down_sync(0xffffffffu, s,  o);
            sq += __shfl_down_sync(0xffffffffu, sq, o);
        }
        __shared__ float ss[8], sqs[8], stats[2];
        int wid = t >> 5, lane = t & 31;
        if (lane == 0) { ss[wid] = s; sqs[wid] = sq; }
        __syncthreads();
        if (t == 0) {
            float S = 0.f, SQ = 0.f;
            #pragma unroll
            for (int i = 0; i < 8; i++) { S += ss[i]; SQ += sqs[i]; }
            float mu = S / (float)D_;
            float var = SQ / (float)D_ - mu * mu;
            stats[0] = mu;
            stats[1] = rsqrtf(var + EPS_);
        }
        __syncthreads();
        float mu = stats[0], rs = stats[1];

        float4 g4 = *(const float4*)(gamma + t * 4);
        float4 b4 = *(const float4*)(beta + t * 4);
        float4 r;
        r.x = (v.x - mu) * rs * g4.x + b4.x;
        r.y = (v.y - mu) * rs * g4.y + b4.y;
        r.z = (v.z - mu) * rs * g4.z + b4.z;
        r.w = (v.w - mu) * rs * g4.w + b4.w;
        float4 p4 = *(const float4*)(pos + (size_t)l * D_ + t * 4);
        r.x += p4.x; r.y += p4.y; r.z += p4.z; r.w += p4.w;
        __half2 h0 = __floats2half2_rn(r.x, r.y);
        __half2 h1 = __floats2half2_rn(r.z, r.w);
        *(uint2*)(out + (size_t)row * D_ + t * 4) = make_uint2(*(uint32_t*)&h0, *(uint32_t*)&h1);
    } else {
        const int M1 = 1 << 20;
        size_t i = ((size_t)(blockIdx.x - B_ * L_) * 256 + t) * 4;   // < 3M
        int which = (int)(i >> 20);
        size_t li = i & (M1 - 1);
        int k = (int)(li >> 10), n = (int)(li & 1023);
        const float* src = (which == 0) ? Wq : (which == 1) ? Wk : Wv;
        float4 v = *(const float4*)(src + li);
        __half2 h0 = __floats2half2_rn(v.x, v.y);
        __half2 h1 = __floats2half2_rn(v.z, v.w);
        *(uint2*)(g_wqkv + (size_t)k * D3_ + which * 1024 + n) =
            make_uint2(*(uint32_t*)&h0, *(uint32_t*)&h1);
    }
}

// ---------------- LayerNorm (standalone, for LN2), output fp16 ----------------
__global__ void ln_kernel(const float* __restrict__ x,
                          const float* __restrict__ gamma,
                          const float* __restrict__ beta,
                          __half* __restrict__ out) {
    int row = blockIdx.x;
    const float* xr = x + (size_t)row * D_;
    int t = threadIdx.x;
    float4 v = *(const float4*)(xr + t * 4);

    float s = v.x + v.y + v.z + v.w;
    float sq = v.x * v.x + v.y * v.y + v.z * v.z + v.w * v.w;
    #pragma unroll
    for (int o = 16; o > 0; o >>= 1) {
        s  += __shfl_down_sync(0xffffffffu, s,  o);
        sq += __shfl_down_sync(0xffffffffu, sq, o);
    }
    __shared__ float ss[8], sqs[8], stats[2];
    int wid = t >> 5, lane = t & 31;
    if (lane == 0) { ss[wid] = s; sqs[wid] = sq; }
    __syncthreads();
    if (t == 0) {
        float S = 0.f, SQ = 0.f;
        #pragma unroll
        for (int i = 0; i < 8; i++) { S += ss[i]; SQ += sqs[i]; }
        float mu = S / (float)D_;
        float var = SQ / (float)D_ - mu * mu;
        stats[0] = mu;
        stats[1] = rsqrtf(var + EPS_);
    }
    __syncthreads();
    float mu = stats[0], rs = stats[1];

    float4 g4 = *(const float4*)(gamma + t * 4);
    float4 b4 = *(const float4*)(beta + t * 4);
    float4 r;
    r.x = (v.x - mu) * rs * g4.x + b4.x;
    r.y = (v.y - mu) * rs * g4.y + b4.y;
    r.z = (v.z - mu) * rs * g4.z + b4.z;
    r.w = (v.w - mu) * rs * g4.w + b4.w;
    __half2 h0 = __floats2half2_rn(r.x, r.y);
    __half2 h1 = __floats2half2_rn(r.z, r.w);
    *(uint2*)(out + (size_t)row * D_ + t * 4) = make_uint2(*(uint32_t*)&h0, *(uint32_t*)&h1);
}

// ---------------- fp16 mma GEMM: 128x128, BK=64, 3-stage, frag double-buffer ----------------
#define AST 72
#define BSTN 136
#define A_STAGE_H (128 * AST)
#define B_STAGE_H (64 * BSTN)
#define STAGE_H (A_STAGE_H + B_STAGE_H)
#define GEMM_SMEM_BYTES (3 * STAGE_H * 2 + 128 * 4)

__global__ __launch_bounds__(256, 2)
void gemm_mma(const __half* __restrict__ A, const __half* __restrict__ W,
              const float* __restrict__ bias, const float* __restrict__ addsrc,
              void* __restrict__ Cout, int M, int N, int K, int flags) {
    extern __shared__ __half smh[];
    float* bias_s = (float*)(smh + 3 * STAGE_H);

    int t = threadIdx.x;
    int wid = t >> 5, lane = t & 31;
    int wm = wid & 1, wn = wid >> 1;
    int gid = lane >> 2, tig = lane & 3;
    int n0 = blockIdx.x * 128, m0 = blockIdx.y * 128;

    uint32_t sA[3], sB[3];
    #pragma unroll
    for (int i = 0; i < 3; i++) {
        sA[i] = smem_u32(smh + i * STAGE_H);
        sB[i] = sA[i] + A_STAGE_H * 2;
    }

    if (t < 32) {
        float4 bv = bias ? *(const float4*)(bias + n0 + t * 4) : make_float4(0.f, 0.f, 0.f, 0.f);
        *(float4*)(bias_s + t * 4) = bv;
    }

    int rsel = lane & 7;
    int t01  = (lane >> 3) & 1;
    int t23  = (lane >> 4) & 1;
    uint32_t aoff[4];
    #pragma unroll
    for (int mf = 0; mf < 4; mf++)
        aoff[mf] = (uint32_t)(((wm * 64 + mf * 16 + t01 * 8 + rsel) * AST + t23 * 8) * 2);
    uint32_t boff[2];
    #pragma unroll
    for (int nf2 = 0; nf2 < 2; nf2++)
        boff[nf2] = (uint32_t)(((t01 * 8 + rsel) * BSTN + wn * 32 + nf2 * 16 + t23 * 8) * 2);

    #define LOAD_TILE(buf, kk0) do { \
        _Pragma("unroll") \
        for (int j = 0; j < 4; j++) { \
            int id = t + j * 256; \
            int row = id >> 3, c4 = id & 7; \
            CP_ASYNC16(sA[buf] + (uint32_t)(row * AST + c4 * 8) * 2u, \
                       A + (size_t)(m0 + row) * K + (kk0) + c4 * 8); \
        } \
        _Pragma("unroll") \
        for (int j = 0; j < 4; j++) { \
            int id = t + j * 256; \
            int row = id >> 4, c = id & 15; \
            CP_ASYNC16(sB[buf] + (uint32_t)(row * BSTN + c * 8) * 2u, \
                       W + (size_t)((kk0) + row) * N + n0 + c * 8); \
        } \
        CP_COMMIT(); \
    } while (0)

    #define LDFRAG(dstA, dstB, sbuf, kk) do { \
        uint32_t _kaddA = (uint32_t)((kk) * 32); \
        uint32_t _kaddB = (uint32_t)((kk) * 16 * BSTN * 2); \
        _Pragma("unroll") \
        for (int mf = 0; mf < 4; mf++) \
            ldsm_x4((dstA)[mf], sA[sbuf] + aoff[mf] + _kaddA); \
        ldsm_x4_t((dstB)[0], sB[sbuf] + boff[0] + _kaddB); \
        ldsm_x4_t((dstB)[1], sB[sbuf] + boff[1] + _kaddB); \
    } while (0)

    float acc[4][4][4];
    #pragma unroll
    for (int i = 0; i < 4; i++)
        #pragma unroll
        for (int j = 0; j < 4; j++)
            #pragma unroll
            for (int c = 0; c < 4; c++) acc[i][j][c] = 0.f;

    const int NS = K >> 6;
    LOAD_TILE(0, 0);
    LOAD_TILE(1, 64);

    uint32_t afr[2][4][4];
    uint32_t bfr[2][2][4];

    int buf = 0;
    for (int s = 0; s < NS; s++) {
        if (s < NS - 1) { CP_WAIT(1); } else { CP_WAIT(0); }
        __syncthreads();
        if (s + 2 < NS) {
            int nb = (buf + 2 >= 3) ? buf - 1 : buf + 2;
            LOAD_TILE(nb, (s + 2) << 6);
        }

        LDFRAG(afr[0], bfr[0], buf, 0);

        #pragma unroll
        for (int kk = 0; kk < 4; kk++) {
            int cur = kk & 1, nxt = cur ^ 1;
            if (kk < 3) LDFRAG(afr[nxt], bfr[nxt], buf, kk + 1);
            #pragma unroll
            for (int nf2 = 0; nf2 < 2; nf2++) {
                #pragma unroll
                for (int mf = 0; mf < 4; mf++) {
                    mma_f16(acc[mf][nf2 * 2],     afr[cur][mf], bfr[cur][nf2][0], bfr[cur][nf2][1]);
                    mma_f16(acc[mf][nf2 * 2 + 1], afr[cur][mf], bfr[cur][nf2][2], bfr[cur][nf2][3]);
                }
            }
        }
        buf = (buf + 1 >= 3) ? 0 : buf + 1;
    }

    bool do_gelu = (flags & 1), out_half = (flags & 4);
    float* Cf = (float*)Cout;
    __half* Ch = (__half*)Cout;
    int row_base = m0 + wm * 64 + gid;
    int colw = wn * 32;
    #pragma unroll
    for (int mf = 0; mf < 4; mf++) {
        #pragma unroll
        for (int rr = 0; rr < 2; rr++) {
            int grow = row_base + mf * 16 + rr * 8;
            size_t roff = (size_t)grow * N + n0 + colw;
            #pragma unroll
            for (int nf = 0; nf < 4; nf++) {
                int cl = colw + nf * 8 + tig * 2;
                float v0 = acc[mf][nf][rr * 2 + 0] + bias_s[cl];
                float v1 = acc[mf][nf][rr * 2 + 1] + bias_s[cl + 1];
                if (do_gelu) {
                    v0 = 0.5f * v0 * (1.f + erff(v0 * 0.70710678118654752f));
                    v1 = 0.5f * v1 * (1.f + erff(v1 * 0.70710678118654752f));
                }
                if (addsrc) {
                    float2 sv = *(const float2*)(addsrc + roff + nf * 8 + tig * 2);
                    v0 += sv.x; v1 += sv.y;
                }
                if (out_half) {
                    __half2 hv = __floats2half2_rn(v0, v1);
                    *(__half2*)(Ch + roff + nf * 8 + tig * 2) = hv;
                } else {
                    *(float2*)(Cf + roff + nf * 8 + tig * 2) = make_float2(v0, v1);
                }
            }
        }
    }
    #undef LOAD_TILE
    #undef LDFRAG
}

// ---------------- fused attention (FA2, base-2) + Wo/W1/W2 convert filler blocks ----------------
// grid (16, 37): blockIdx.y < 32 -> attention; else 80 convert blocks fill idle wave-2 slots.
#define ST_ 72
#define ATT_SMEM ((128 * ST_ + 4 * 64 * ST_) * 2)
#define CONV_CHUNKS (9u * (1u << 20) / 4u)   // 9M floats as float4 chunks = 2359296
#define CONV_BLOCKS 80
#define CONV_STRIDE (CONV_BLOCKS * 256)

__global__ __launch_bounds__(256)
void attn_mma(const __half* __restrict__ qkv, __half* __restrict__ o,
              const float* __restrict__ Wo, const float* __restrict__ W1,
              const float* __restrict__ W2) {
    int t = threadIdx.x;

    if (blockIdx.y >= 32) {
        // ---- weight convert filler: Wo (1M) | W1 (4M) | W2 (4M), flat fp32->fp16 ----
        const size_t M1 = 1 << 20;
        int cb = (blockIdx.y - 32) * 16 + blockIdx.x;    // 0..79
        for (size_t c = (size_t)cb * 256 + t; c < CONV_CHUNKS; c += CONV_STRIDE) {
            size_t e = c * 4;
            const float* src;
            __half* dst;
            size_t off;
            if (e < M1)            { src = Wo; dst = g_woh; off = e; }
            else if (e < 5 * M1)   { src = W1; dst = g_w1h; off = e - M1; }
            else                   { src = W2; dst = g_w2h; off = e - 5 * M1; }
            float4 v = *(const float4*)(src + off);
            __half2 h0 = __floats2half2_rn(v.x, v.y);
            __half2 h1 = __floats2half2_rn(v.z, v.w);
            *(uint2*)(dst + off) = make_uint2(*(uint32_t*)&h0, *(uint32_t*)&h1);
        }
        return;
    }

    extern __shared__ __half smh[];
    __half* Qs = smh;
    uint32_t uQ = smem_u32(Qs);
    uint32_t uK0 = uQ + 128 * ST_ * 2;
    uint32_t uV0 = uK0 + 2 * 64 * ST_ * 2;
    const uint32_t KVBUF = 64 * ST_ * 2;

    int w = t >> 5, lane = t & 31;
    int gid = lane >> 2, tig = lane & 3;
    int bh = blockIdx.y;
    int b = bh >> 4, h = bh & 15;
    int q0 = blockIdx.x * 128;
    int qrow = w * 16;
    size_t qbase = ((size_t)b * L_) * D3_ + (size_t)h * DH_;
    size_t obase = ((size_t)b * L_) * D_ + (size_t)h * DH_;

    int rsel = lane & 7;
    int t01  = (lane >> 3) & 1;
    int t23  = (lane >> 4) & 1;
    uint32_t qaoff = (uint32_t)(((qrow + t01 * 8 + rsel) * ST_ + t23 * 8) * 2);
    uint32_t kboff[4], vboff[4];
    #pragma unroll
    for (int nf2 = 0; nf2 < 4; nf2++) {
        kboff[nf2] = (uint32_t)(((nf2 * 16 + t01 * 8 + rsel) * ST_ + t23 * 8) * 2);
        vboff[nf2] = (uint32_t)(((t01 * 8 + rsel) * ST_ + nf2 * 16 + t23 * 8) * 2);
    }

    const __half2 sc2 = __floats2half2_rn(0.125f * LOG2E, 0.125f * LOG2E);
    #pragma unroll
    for (int j = 0; j < 4; j++) {
        int i = t + j * 256;
        int r = i >> 3, c4 = i & 7;
        uint4 v = *(const uint4*)(qkv + qbase + (size_t)(q0 + r) * D3_ + c4 * 8);
        __half2* hp = (__half2*)&v;
        hp[0] = __hmul2(hp[0], sc2); hp[1] = __hmul2(hp[1], sc2);
        hp[2] = __hmul2(hp[2], sc2); hp[3] = __hmul2(hp[3], sc2);
        *(uint4*)(Qs + r * ST_ + c4 * 8) = v;
    }

    #define LOADKV(buf, k0v) do { \
        _Pragma("unroll") \
        for (int j = 0; j < 2; j++) { \
            int id = t + j * 256; \
            int row = id >> 3, c4 = id & 7; \
            uint32_t soff = (uint32_t)(row * ST_ + c4 * 8) * 2u + (buf) * KVBUF; \
            CP_ASYNC16(uK0 + soff, qkv + qbase + 1024 + (size_t)((k0v) + row) * D3_ + c4 * 8); \
            CP_ASYNC16(uV0 + soff, qkv + qbase + 2048 + (size_t)((k0v) + row) * D3_ + c4 * 8); \
        } \
        CP_COMMIT(); \
    } while (0)

    float oacc[8][4];
    #pragma unroll
    for (int i = 0; i < 8; i++)
        #pragma unroll
        for (int j = 0; j < 4; j++) oacc[i][j] = 0.f;
    float m0 = -INFINITY, m1 = -INFINITY, l0 = 0.f, l1 = 0.f;

    LOADKV(0, 0);

    for (int k0 = 0; k0 < L_; k0 += 64) {
        CP_WAIT(0);
        __syncthreads();
        int buf = (k0 >> 6) & 1;
        if (k0 + 64 < L_) LOADKV(buf ^ 1, k0 + 64);
        uint32_t uK = uK0 + buf * KVBUF;
        uint32_t uV = uV0 + buf * KVBUF;

        float sacc[8][4];
        #pragma unroll
        for (int i = 0; i < 8; i++)
            #pragma unroll
            for (int j = 0; j < 4; j++) sacc[i][j] = 0.f;
        #pragma unroll
        for (int kk = 0; kk < 4; kk++) {
            uint32_t kadd = (uint32_t)(kk * 32);
            uint32_t af[4];
            ldsm_x4(af, uQ + qaoff + kadd);
            #pragma unroll
            for (int nf2 = 0; nf2 < 4; nf2++) {
                uint32_t bf[4];
                ldsm_x4(bf, uK + kboff[nf2] + kadd);
                mma_f16(sacc[nf2 * 2],     af, bf[0], bf[2]);
                mma_f16(sacc[nf2 * 2 + 1], af, bf[1], bf[3]);
            }
        }

        float mx0 = -INFINITY, mx1 = -INFINITY;
        #pragma unroll
        for (int nf = 0; nf < 8; nf++) {
            mx0 = fmaxf(mx0, fmaxf(sacc[nf][0], sacc[nf][1]));
            mx1 = fmaxf(mx1, fmaxf(sacc[nf][2], sacc[nf][3]));
        }
        mx0 = fmaxf(mx0, __shfl_xor_sync(0xffffffffu, mx0, 1));
        mx0 = fmaxf(mx0, __shfl_xor_sync(0xffffffffu, mx0, 2));
        mx1 = fmaxf(mx1, __shfl_xor_sync(0xffffffffu, mx1, 1));
        mx1 = fmaxf(mx1, __shfl_xor_sync(0xffffffffu, mx1, 2));
        float mn0 = fmaxf(m0, mx0), mn1 = fmaxf(m1, mx1);
        float al0 = ex2(m0 - mn0), al1 = ex2(m1 - mn1);
        m0 = mn0; m1 = mn1;

        uint32_t ph[8][2];
        float sum0 = 0.f, sum1 = 0.f;
        #pragma unroll
        for (int nf = 0; nf < 8; nf++) {
            float p00 = ex2(sacc[nf][0] - m0);
            float p01 = ex2(sacc[nf][1] - m0);
            float p10 = ex2(sacc[nf][2] - m1);
            float p11 = ex2(sacc[nf][3] - m1);
            sum0 += p00 + p01;
            sum1 += p10 + p11;
            __half2 h0 = __floats2half2_rn(p00, p01);
            __half2 h1 = __floats2half2_rn(p10, p11);
            ph[nf][0] = *(uint32_t*)&h0;
            ph[nf][1] = *(uint32_t*)&h1;
        }
        sum0 += __shfl_xor_sync(0xffffffffu, sum0, 1);
        sum0 += __shfl_xor_sync(0xffffffffu, sum0, 2);
        sum1 += __shfl_xor_sync(0xffffffffu, sum1, 1);
        sum1 += __shfl_xor_sync(0xffffffffu, sum1, 2);
        l0 = l0 * al0 + sum0;
        l1 = l1 * al1 + sum1;

        #pragma unroll
        for (int nf = 0; nf < 8; nf++) {
            oacc[nf][0] *= al0; oacc[nf][1] *= al0;
            oacc[nf][2] *= al1; oacc[nf][3] *= al1;
        }

        #pragma unroll
        for (int kk = 0; kk < 4; kk++) {
            uint32_t af[4] = { ph[2 * kk][0], ph[2 * kk][1], ph[2 * kk + 1][0], ph[2 * kk + 1][1] };
            uint32_t kaddv = (uint32_t)(kk * 16 * ST_ * 2);
            #pragma unroll
            for (int nf2 = 0; nf2 < 4; nf2++) {
                uint32_t bf[4];
                ldsm_x4_t(bf, uV + vboff[nf2] + kaddv);
                mma_f16(oacc[nf2 * 2],     af, bf[0], bf[1]);
                mma_f16(oacc[nf2 * 2 + 1], af, bf[2], bf[3]);
            }
        }
    }

    float inv0 = 1.f / l0, inv1 = 1.f / l1;
    size_t r0off = obase + (size_t)(q0 + qrow + gid) * D_;
    size_t r1off = obase + (size_t)(q0 + qrow + gid + 8) * D_;
    #pragma unroll
    for (int nf = 0; nf < 8; nf++) {
        int c = nf * 8 + tig * 2;
        *(__half2*)(o + r0off + c) = __floats2half2_rn(oacc[nf][0] * inv0, oacc[nf][1] * inv0);
        *(__half2*)(o + r1off + c) = __floats2half2_rn(oacc[nf][2] * inv1, oacc[nf][3] * inv1);
    }
    #undef LOADKV
}

// ---------------- launch ----------------
extern "C" void kernel_launch(void* const* d_in, const int* in_sizes, int n_in,
                              void* d_out, int out_size) {
    const float* x     = (const float*)d_in[0];
    const float* pos   = (const float*)d_in[1];
    const float* ln1_g = (const float*)d_in[2];
    const float* ln1_b = (const float*)d_in[3];
    const float* Wq    = (const float*)d_in[4];
    const float* Wk    = (const float*)d_in[5];
    const float* Wv    = (const float*)d_in[6];
    const float* Wo    = (const float*)d_in[7];
    const float* bo    = (const float*)d_in[8];
    const float* ln2_g = (const float*)d_in[9];
    const float* ln2_b = (const float*)d_in[10];
    const float* W1    = (const float*)d_in[11];
    const float* b1    = (const float*)d_in[12];
    const float* W2    = (const float*)d_in[13];
    const float* b2    = (const float*)d_in[14];
    float* out = (float*)d_out;

    __half *h, *qkv, *ao, *ff, *wqkv, *woh, *w1h, *w2h;
    float *x2;
    cudaGetSymbolAddress((void**)&h,    g_h);
    cudaGetSymbolAddress((void**)&qkv,  g_qkv);
    cudaGetSymbolAddress((void**)&ao,   g_ao);
    cudaGetSymbolAddress((void**)&x2,   g_x2);
    cudaGetSymbolAddress((void**)&ff,   g_ff);
    cudaGetSymbolAddress((void**)&wqkv, g_wqkv);
    cudaGetSymbolAddress((void**)&woh,  g_woh);
    cudaGetSymbolAddress((void**)&w1h,  g_w1h);
    cudaGetSymbolAddress((void**)&w2h,  g_w2h);

    cudaFuncSetAttribute(gemm_mma, cudaFuncAttributeMaxDynamicSharedMemorySize, GEMM_SMEM_BYTES);
    cudaFuncSetAttribute(attn_mma, cudaFuncAttributeMaxDynamicSharedMemorySize, ATT_SMEM);

    const int ROWS = B_ * L_;   // 4096

    // 0+1) fused: h = fp16(LN1(x) + pos)  AND  qkv-weight interleave convert
    prep_kernel<<<ROWS + 3072, 256>>>(x, ln1_g, ln1_b, pos, h, Wq, Wk, Wv, wqkv);

    // 2) fused qkv = h @ [Wq|Wk|Wv]  (half out)
    {
        dim3 grid(D3_ / 128, ROWS / 128);
        gemm_mma<<<grid, 256, GEMM_SMEM_BYTES>>>(h, wqkv, nullptr, nullptr, qkv, ROWS, D3_, D_, 4);
    }

    // 3) attention -> ao (half); Wo/W1/W2 converts ride along in idle wave-2 slots
    {
        dim3 grid(L_ / 128, B_ * H_ + 5);   // +5 rows of 16 = 80 convert blocks
        attn_mma<<<grid, 256, ATT_SMEM>>>(qkv, ao, Wo, W1, W2);
    }

    // 4) x2 = x + ao @ Wo + bo  (float out, exact residual)
    {
        dim3 grid(D_ / 128, ROWS / 128);
        gemm_mma<<<grid, 256, GEMM_SMEM_BYTES>>>(ao, woh, bo, x, x2, ROWS, D_, D_, 0);
    }

    // 5) h = fp16(LN2(x2))
    ln_kernel<<<ROWS, 256>>>(x2, ln2_g, ln2_b, h);

    // 6) ff = fp16(gelu(h @ W1 + b1))
    {
        dim3 grid(FF_ / 128, ROWS / 128);
        gemm_mma<<<grid, 256, GEMM_SMEM_BYTES>>>(h, w1h, b1, nullptr, ff, ROWS, FF_, D_, 5);
    }

    // 7) out = x2 + ff @ W2 + b2  (float out)
    {
        dim3 grid(D_ / 128, ROWS / 128);
        gemm_mma<<<grid, 256, GEMM_SMEM_BYTES>>>(ff, w2h, b2, x2, out, ROWS, D_, FF_, 0);
    }
}